// round 2
// baseline (speedup 1.0000x reference)
#include <cuda_runtime.h>
#include <math.h>

#define NB   32
#define NS   4096
#define ND   64
#define NL   13
#define NWR  13
#define NHF  128
#define NCLS 2
#define ROWS (NB*NS)          // 131072
#define SD   (NS*ND)          // 262144

typedef unsigned long long ull;

// Scratch
__device__ float g_X[(size_t)ROWS*ND];              // 32 MB
__device__ float g_Ft[(size_t)NWR*NL*ROWS];         // 84.5 MB, layout [k][l][row]
__device__ float g_V[(size_t)ROWS*ND];              // 32 MB
__device__ float g_Z0[(size_t)ROWS*ND];
__device__ float g_Z1[(size_t)ROWS*ND];

__constant__ int c_off[NL] = {0,1,2,4,8,16,32,64,128,256,512,1024,2048};

__device__ __forceinline__ float gelu_exact(float x) {
    return 0.5f * x * (1.0f + erff(x * 0.7071067811865476f));
}
__device__ __forceinline__ ull pack2(float x, float y) {
    ull r; asm("mov.b64 %0, {%1,%2};" : "=l"(r) : "f"(x), "f"(y)); return r;
}
__device__ __forceinline__ ull dup2(float x) { return pack2(x, x); }
__device__ __forceinline__ float2 unpack2(ull v) {
    float2 f; asm("mov.b64 {%0,%1}, %2;" : "=f"(f.x), "=f"(f.y) : "l"(v)); return f;
}
__device__ __forceinline__ void fma2(ull &d, ull a, ull b) {
    asm("fma.rn.f32x2 %0, %1, %2, %3;" : "=l"(d) : "l"(a), "l"(b), "l"(d));
}

// ---------------------------------------------------------------------------
// Embedding gather
// ---------------------------------------------------------------------------
__global__ void embed_kernel(const int* __restrict__ tok,
                             const float* __restrict__ emb) {
    int idx = blockIdx.x * blockDim.x + threadIdx.x;   // over ROWS*16
    int row = idx >> 4;
    int c   = idx & 15;
    int t   = tok[row];
    reinterpret_cast<float4*>(g_X)[idx] =
        reinterpret_cast<const float4*>(emb)[t * 16 + c];
}

// ---------------------------------------------------------------------------
// FNet: 128-row x 128-hidden tile per block, f32x2-packed over row pairs.
// Thread map stage1: lane hg=t&31 -> 4 hidden units (4hg..4hg+3);
//                    warp rg=t>>5 -> 8 row-pairs (8rg..8rg+7).
// smem: Wp (dup-packed W1, lane-major), Xt2 (row-pair-packed X^T),
//       W2t2 (h-pair-packed W2^T), Hs (H, stride 130).
// ---------------------------------------------------------------------------
__global__ __launch_bounds__(256) void fnet_kernel(
    const float* __restrict__ fW1, const float* __restrict__ fb1,
    const float* __restrict__ fW2, const float* __restrict__ fb2) {
    extern __shared__ char smem_raw[];
    ull*   Wp   = (ull*)smem_raw;          // 8192 ull
    ull*   Xt2  = Wp + 8192;               // 4096 ull
    ull*   W2t2 = Xt2 + 4096;              // 832 ull
    float* Hs   = (float*)(W2t2 + 832);    // 128*130 floats
    float* Xtf  = (float*)Xt2;

    const int k    = blockIdx.y;
    const int row0 = blockIdx.x * 128;
    const int t    = threadIdx.x;
    const int hg   = t & 31;
    const int rg   = t >> 5;

    // --- prefill Wp: [(d*4+j)*32 + hg] = dup(fW1[k][d][4hg+j])
    for (int idx = t; idx < 8192; idx += 256) {
        int d = idx >> 7, rem = idx & 127, j = rem >> 5, g = rem & 31;
        Wp[idx] = dup2(fW1[((size_t)k*64 + d)*128 + g*4 + j]);
    }
    // --- prefill Xt (transposed): Xtf[d*128 + r]
    {
        int r = t >> 1, dh = (t & 1) * 32;
        const float4* xrow = (const float4*)(g_X + (size_t)(row0 + r)*64 + dh);
#pragma unroll
        for (int d4 = 0; d4 < 8; d4++) {
            float4 xv = xrow[d4];
            int d = dh + d4*4;
            Xtf[(d+0)*128 + r] = xv.x;
            Xtf[(d+1)*128 + r] = xv.y;
            Xtf[(d+2)*128 + r] = xv.z;
            Xtf[(d+3)*128 + r] = xv.w;
        }
    }
    // --- prefill W2t2: [l*64+hp] = {W2[2hp][l], W2[2hp+1][l]}
    for (int idx = t; idx < 832; idx += 256) {
        int l = idx >> 6, hp = idx & 63;
        W2t2[idx] = pack2(fW2[((size_t)k*128 + 2*hp  )*13 + l],
                          fW2[((size_t)k*128 + 2*hp+1)*13 + l]);
    }
    __syncthreads();

    // --- stage 1: H = gelu(X @ W1 + b1)
    ull acc[4][8];
#pragma unroll
    for (int j = 0; j < 4; j++) {
        ull bj = dup2(fb1[k*128 + hg*4 + j]);
#pragma unroll
        for (int i = 0; i < 8; i++) acc[j][i] = bj;
    }
#pragma unroll 1
    for (int dc = 0; dc < 16; dc++) {
        ull w[4][4];
#pragma unroll
        for (int dd = 0; dd < 4; dd++)
#pragma unroll
            for (int j = 0; j < 4; j++)
                w[dd][j] = Wp[((dc*4+dd)*4 + j)*32 + hg];
#pragma unroll
        for (int dd = 0; dd < 4; dd++) {
            ull x[8];
#pragma unroll
            for (int i = 0; i < 8; i++) x[i] = Xt2[(dc*4+dd)*64 + rg*8 + i];
#pragma unroll
            for (int j = 0; j < 4; j++)
#pragma unroll
                for (int i = 0; i < 8; i++)
                    fma2(acc[j][i], w[dd][j], x[i]);
        }
    }
    // gelu + store H (rows 2rp, 2rp+1; column h)
#pragma unroll
    for (int j = 0; j < 4; j++) {
        int h = hg*4 + j;
#pragma unroll
        for (int i = 0; i < 8; i++) {
            int r0 = (rg*8 + i) * 2;
            float2 v = unpack2(acc[j][i]);
            Hs[(r0  )*130 + h] = gelu_exact(v.x);
            Hs[(r0+1)*130 + h] = gelu_exact(v.y);
        }
    }
    __syncthreads();

    // --- stage 2: F = H @ W2 + b2, pack along h (horizontal add at end)
    {
        int r2 = t & 127, half = t >> 7;
        int nl = 7 - half;                 // half0: l=0,2,..12 (7); half1: 1,3,..11 (6)
        ull acc2[7];
#pragma unroll
        for (int q = 0; q < 7; q++) acc2[q] = 0;
        const ull* hrow = (const ull*)(Hs + (size_t)r2*130);
#pragma unroll 4
        for (int hp = 0; hp < 64; hp++) {
            ull hv = hrow[hp];
#pragma unroll
            for (int q = 0; q < 7; q++)
                if (q < nl) fma2(acc2[q], hv, W2t2[(2*q+half)*64 + hp]);
        }
        for (int q = 0; q < nl; q++) {
            int l = 2*q + half;
            float2 s = unpack2(acc2[q]);
            g_Ft[((size_t)k*NL + l)*ROWS + row0 + r2] = s.x + s.y + fb2[k*NL + l];
        }
    }
}

// ---------------------------------------------------------------------------
// VNet: same stage-1; stage-2 packs along output dim d (pairs from vW2 rows).
// ---------------------------------------------------------------------------
__global__ __launch_bounds__(256) void vnet_kernel(
    const float* __restrict__ vW1, const float* __restrict__ vb1,
    const float* __restrict__ vW2, const float* __restrict__ vb2) {
    extern __shared__ char smem_raw[];
    ull*   Wp   = (ull*)smem_raw;          // 8192 ull
    ull*   Xt2  = Wp + 8192;               // 4096 ull
    ull*   W2s2 = Xt2 + 4096;              // 4096 ull (vW2 as ull pairs)
    float* Hs   = (float*)(W2s2 + 4096);   // 128*130
    float* Xtf  = (float*)Xt2;

    const int row0 = blockIdx.x * 128;
    const int t    = threadIdx.x;
    const int hg   = t & 31;
    const int rg   = t >> 5;

    for (int idx = t; idx < 8192; idx += 256) {
        int d = idx >> 7, rem = idx & 127, j = rem >> 5, g = rem & 31;
        Wp[idx] = dup2(vW1[(size_t)d*128 + g*4 + j]);
    }
    {
        int r = t >> 1, dh = (t & 1) * 32;
        const float4* xrow = (const float4*)(g_X + (size_t)(row0 + r)*64 + dh);
#pragma unroll
        for (int d4 = 0; d4 < 8; d4++) {
            float4 xv = xrow[d4];
            int d = dh + d4*4;
            Xtf[(d+0)*128 + r] = xv.x;
            Xtf[(d+1)*128 + r] = xv.y;
            Xtf[(d+2)*128 + r] = xv.z;
            Xtf[(d+3)*128 + r] = xv.w;
        }
    }
    for (int idx = t; idx < 4096; idx += 256)
        W2s2[idx] = ((const ull*)vW2)[idx];
    __syncthreads();

    ull acc[4][8];
#pragma unroll
    for (int j = 0; j < 4; j++) {
        ull bj = dup2(vb1[hg*4 + j]);
#pragma unroll
        for (int i = 0; i < 8; i++) acc[j][i] = bj;
    }
#pragma unroll 1
    for (int dc = 0; dc < 16; dc++) {
        ull w[4][4];
#pragma unroll
        for (int dd = 0; dd < 4; dd++)
#pragma unroll
            for (int j = 0; j < 4; j++)
                w[dd][j] = Wp[((dc*4+dd)*4 + j)*32 + hg];
#pragma unroll
        for (int dd = 0; dd < 4; dd++) {
            ull x[8];
#pragma unroll
            for (int i = 0; i < 8; i++) x[i] = Xt2[(dc*4+dd)*64 + rg*8 + i];
#pragma unroll
            for (int j = 0; j < 4; j++)
#pragma unroll
                for (int i = 0; i < 8; i++)
                    fma2(acc[j][i], w[dd][j], x[i]);
        }
    }
#pragma unroll
    for (int j = 0; j < 4; j++) {
        int h = hg*4 + j;
#pragma unroll
        for (int i = 0; i < 8; i++) {
            int r0 = (rg*8 + i) * 2;
            float2 v = unpack2(acc[j][i]);
            Hs[(r0  )*130 + h] = gelu_exact(v.x);
            Hs[(r0+1)*130 + h] = gelu_exact(v.y);
        }
    }
    __syncthreads();

    // stage 2: V = H @ vW2 + vb2 ; thread = (dpq 0..15, rg2 0..15 -> 8 rows)
    {
        int dpq = t & 15, rg2 = t >> 4;
        ull acc2[8][2];
#pragma unroll
        for (int m = 0; m < 8; m++) {
            acc2[m][0] = ((const ull*)vb2)[2*dpq];
            acc2[m][1] = ((const ull*)vb2)[2*dpq + 1];
        }
#pragma unroll 4
        for (int h = 0; h < 128; h++) {
            ull w0 = W2s2[h*32 + 2*dpq];
            ull w1 = W2s2[h*32 + 2*dpq + 1];
#pragma unroll
            for (int m = 0; m < 8; m++) {
                ull h2 = dup2(Hs[(rg2*8 + m)*130 + h]);
                fma2(acc2[m][0], h2, w0);
                fma2(acc2[m][1], h2, w1);
            }
        }
#pragma unroll
        for (int m = 0; m < 8; m++) {
            size_t base = ((size_t)(row0 + rg2*8 + m))*32;
            ((ull*)g_V)[base + 2*dpq    ] = acc2[m][0];
            ((ull*)g_V)[base + 2*dpq + 1] = acc2[m][1];
        }
    }
}

// ---------------------------------------------------------------------------
// Chord round, smem-staged: block = (b, cp in 0..8), Z slice 4096x8 floats in
// smem with 48B row stride (conflict-free strided LDS.128 gathers).
// Ft layout [l][row] -> coalesced F reads.
// ---------------------------------------------------------------------------
__global__ __launch_bounds__(512) void chord_kernel(
    const float* __restrict__ Ft, const float* __restrict__ Zin,
    const float* __restrict__ V, float* __restrict__ Zout) {
    extern __shared__ float Zs[];          // 4096 * 12 floats (8 used per row)
    const int t  = threadIdx.x;
    const int b  = blockIdx.x >> 3;
    const int cp = blockIdx.x & 7;

    const float4* Zg = (const float4*)Zin + ((size_t)b*NS)*16 + cp*2;
    float4* Zs4 = (float4*)Zs;
#pragma unroll
    for (int m = 0; m < 16; m++) {
        int fi = t + 512*m;
        int i = fi >> 1, q = fi & 1;
        Zs4[i*3 + q] = Zg[(size_t)i*16 + q];
    }
    __syncthreads();

    const float* Fb = Ft + (size_t)b*NS;
#pragma unroll 1
    for (int m = 0; m < 8; m++) {
        int i = t + 512*m;
        float4 a0 = make_float4(0.f,0.f,0.f,0.f);
        float4 a1 = make_float4(0.f,0.f,0.f,0.f);
#pragma unroll
        for (int l = 0; l < NL; l++) {
            float fv = __ldg(Fb + (size_t)l*ROWS + i);
            int jj = (i + c_off[l]) & (NS - 1);
            float4 z0 = Zs4[jj*3];
            float4 z1 = Zs4[jj*3 + 1];
            a0.x = fmaf(fv, z0.x, a0.x); a0.y = fmaf(fv, z0.y, a0.y);
            a0.z = fmaf(fv, z0.z, a0.z); a0.w = fmaf(fv, z0.w, a0.w);
            a1.x = fmaf(fv, z1.x, a1.x); a1.y = fmaf(fv, z1.y, a1.y);
            a1.z = fmaf(fv, z1.z, a1.z); a1.w = fmaf(fv, z1.w, a1.w);
        }
        size_t gi = ((size_t)(b*NS + i))*16 + cp*2;
        float4 v0 = ((const float4*)V)[gi];
        float4 v1 = ((const float4*)V)[gi + 1];
        a0.x += v0.x; a0.y += v0.y; a0.z += v0.z; a0.w += v0.w;
        a1.x += v1.x; a1.y += v1.y; a1.z += v1.z; a1.w += v1.w;
        ((float4*)Zout)[gi]     = a0;
        ((float4*)Zout)[gi + 1] = a1;
    }
}

// ---------------------------------------------------------------------------
// Logits: out[b,c] = dot(V[b], finW[c]) + finb[c], split 8x + atomicAdd
// ---------------------------------------------------------------------------
__global__ __launch_bounds__(256) void logits_kernel(
    const float* __restrict__ finW, const float* __restrict__ finb,
    float* __restrict__ out) {
    const int s = blockIdx.x & 7;
    const int c = (blockIdx.x >> 3) & 1;
    const int b = blockIdx.x >> 4;
    const int t = threadIdx.x;
    const int chunk = SD/4/8;              // 8192 float4

    const float4* v = (const float4*)(g_V  + (size_t)b*SD) + s*chunk;
    const float4* w = (const float4*)(finW + (size_t)c*SD) + s*chunk;
    float acc = 0.f;
    for (int i = t; i < chunk; i += 256) {
        float4 vv = v[i], ww = w[i];
        acc = fmaf(vv.x, ww.x, acc);
        acc = fmaf(vv.y, ww.y, acc);
        acc = fmaf(vv.z, ww.z, acc);
        acc = fmaf(vv.w, ww.w, acc);
    }
    __shared__ float red[256];
    red[t] = acc;
    __syncthreads();
#pragma unroll
    for (int sft = 128; sft > 0; sft >>= 1) {
        if (t < sft) red[t] += red[t + sft];
        __syncthreads();
    }
    if (t == 0) {
        float val = red[0] + (s == 0 ? finb[c] : 0.f);
        atomicAdd(&out[b*NCLS + c], val);
    }
}

// ---------------------------------------------------------------------------
extern "C" void kernel_launch(void* const* d_in, const int* in_sizes, int n_in,
                              void* d_out, int out_size) {
    const int*   tok  = (const int*)  d_in[0];
    const float* emb  = (const float*)d_in[1];
    const float* fW1  = (const float*)d_in[2];
    const float* fb1  = (const float*)d_in[3];
    const float* fW2  = (const float*)d_in[4];
    const float* fb2  = (const float*)d_in[5];
    const float* vW1  = (const float*)d_in[6];
    const float* vb1  = (const float*)d_in[7];
    const float* vW2  = (const float*)d_in[8];
    const float* vb2  = (const float*)d_in[9];
    const float* finW = (const float*)d_in[10];
    const float* finb = (const float*)d_in[11];
    float* out = (float*)d_out;

    const int fnet_smem  = 8192*8 + 4096*8 + 832*8 + 128*130*4;   // 171520
    const int vnet_smem  = 8192*8 + 4096*8 + 4096*8 + 128*130*4;  // 197632
    const int chord_smem = NS * 12 * 4;                           // 196608
    cudaFuncSetAttribute(fnet_kernel,  cudaFuncAttributeMaxDynamicSharedMemorySize, fnet_smem);
    cudaFuncSetAttribute(vnet_kernel,  cudaFuncAttributeMaxDynamicSharedMemorySize, vnet_smem);
    cudaFuncSetAttribute(chord_kernel, cudaFuncAttributeMaxDynamicSharedMemorySize, chord_smem);

    embed_kernel<<<ROWS*16/256, 256>>>(tok, emb);

    dim3 fgrid(ROWS/128, NWR);
    fnet_kernel<<<fgrid, 256, fnet_smem>>>(fW1, fb1, fW2, fb2);
    vnet_kernel<<<ROWS/128, 256, vnet_smem>>>(vW1, vb1, vW2, vb2);

    cudaMemsetAsync(out, 0, NB*NCLS*sizeof(float));
    logits_kernel<<<NB*NCLS*8, 256>>>(finW, finb, out);

    float *pV, *pZ0, *pZ1, *pF;
    cudaGetSymbolAddress((void**)&pV,  g_V);
    cudaGetSymbolAddress((void**)&pZ0, g_Z0);
    cudaGetSymbolAddress((void**)&pZ1, g_Z1);
    cudaGetSymbolAddress((void**)&pF,  g_Ft);

    const bool bigOut = (out_size >= NB*NCLS + ROWS*ND);
    const float* zin = pV;
    for (int k = 0; k < NWR; k++) {
        float* zout;
        if (k == NWR - 1 && bigOut) zout = out + NB*NCLS;
        else                        zout = (k & 1) ? pZ1 : pZ0;
        chord_kernel<<<NB*8, 512, chord_smem>>>(pF + (size_t)k*NL*ROWS, zin, pV, zout);
        zin = zout;
    }
}

// round 3
// speedup vs baseline: 4.6863x; 4.6863x over previous
#include <cuda_runtime.h>
#include <math.h>

#define NB   32
#define NS   4096
#define ND   64
#define NL   13
#define NWR  13
#define NCLS 2
#define ROWS (NB*NS)          // 131072
#define SD   (NS*ND)          // 262144
#define VOCAB 512

// Tables (tiny) + fallback Z dump
__device__ float g_Vtab[VOCAB*ND];          // 128 KB
__device__ float g_Ftab[(size_t)NWR*VOCAB*16];  // 13*512*16 floats (rows padded to 16)
__device__ float g_Zdump[(size_t)ROWS*ND];  // only used if out buffer lacks Z space

__device__ __forceinline__ float gelu_exact(float x) {
    return 0.5f * x * (1.0f + erff(x * 0.7071067811865476f));
}

// ---------------------------------------------------------------------------
// Build Vtab (y==0) and Ftab[k] (y==1..13). grid=(4,14), block=128.
// smem: Es[128*64] | W1s[64*128] | Hs[128*128] | W2s[<=128*64]
// ---------------------------------------------------------------------------
__global__ __launch_bounds__(128) void tables_kernel(
    const float* __restrict__ emb,
    const float* __restrict__ fW1, const float* __restrict__ fb1,
    const float* __restrict__ fW2, const float* __restrict__ fb2,
    const float* __restrict__ vW1, const float* __restrict__ vb1,
    const float* __restrict__ vW2, const float* __restrict__ vb2) {
    extern __shared__ float sm[];
    float* Es  = sm;            // 8192
    float* W1s = sm + 8192;     // 8192
    float* Hs  = sm + 16384;    // 16384
    float* W2s = sm + 32768;    // up to 8192

    const int y  = blockIdx.y;
    const int v0 = blockIdx.x * 128;
    const int t  = threadIdx.x;

    for (int idx = t; idx < 8192; idx += 128) Es[idx] = emb[v0*64 + idx];
    const float* W1g = (y == 0) ? vW1 : fW1 + (size_t)(y-1)*64*128;
    for (int idx = t; idx < 8192; idx += 128) W1s[idx] = W1g[idx];
    if (y == 0) {
        for (int idx = t; idx < 8192; idx += 128) W2s[idx] = vW2[idx];
    } else {
        const float* W2g = fW2 + (size_t)(y-1)*128*NL;
        for (int idx = t; idx < 128*NL; idx += 128) W2s[idx] = W2g[idx];
    }
    const float b1 = (y == 0) ? vb1[t] : fb1[(y-1)*128 + t];
    __syncthreads();

    // stage 1: H[r][t] = gelu(emb[r] . W1[:,t] + b1)
    for (int r = 0; r < 128; r++) {
        float acc = b1;
#pragma unroll 16
        for (int d = 0; d < 64; d++) acc = fmaf(Es[r*64 + d], W1s[d*128 + t], acc);
        Hs[r*128 + t] = gelu_exact(acc);
    }
    __syncthreads();

    if (y == 0) {
        for (int o = t; o < 128*64; o += 128) {
            int r = o >> 6, d = o & 63;
            float acc = vb2[d];
#pragma unroll 16
            for (int h = 0; h < 128; h++) acc = fmaf(Hs[r*128 + h], W2s[h*64 + d], acc);
            g_Vtab[(size_t)(v0 + r)*64 + d] = acc;
        }
    } else {
        int k = y - 1;
        for (int o = t; o < 128*NL; o += 128) {
            int r = o / NL, l = o - r*NL;
            float acc = fb2[k*NL + l];
#pragma unroll 16
            for (int h = 0; h < 128; h++) acc = fmaf(Hs[r*128 + h], W2s[h*NL + l], acc);
            g_Ftab[((size_t)k*VOCAB + v0 + r)*16 + l] = acc;
        }
    }
}

// ---------------------------------------------------------------------------
// Logits: out[b,c] = sum_s Vtab[tok[b,s]] . finW[c, s*64:(s+1)*64] + finb[c]
// Split 8 ways along s + atomicAdd. DRAM-bound on finW.
// ---------------------------------------------------------------------------
__global__ __launch_bounds__(256) void logits_kernel(
    const int* __restrict__ tok,
    const float* __restrict__ finW, const float* __restrict__ finb,
    float* __restrict__ out) {
    const int s = blockIdx.x & 7;
    const int c = (blockIdx.x >> 3) & 1;
    const int b = blockIdx.x >> 4;
    const int t = threadIdx.x;
    const int chunk = SD/4/8;   // 8192 float4

    const float4* Vt4 = (const float4*)g_Vtab;
    const float4* w   = (const float4*)(finW + (size_t)c*SD) + s*chunk;
    const int*    tkb = tok + (size_t)b*NS;

    float acc = 0.f;
    for (int i = t; i < chunk; i += 256) {
        int gi   = s*chunk + i;
        int srow = gi >> 4;
        int d4   = gi & 15;
        float4 vv = Vt4[tkb[srow]*16 + d4];
        float4 ww = w[i];
        acc = fmaf(vv.x, ww.x, acc);
        acc = fmaf(vv.y, ww.y, acc);
        acc = fmaf(vv.z, ww.z, acc);
        acc = fmaf(vv.w, ww.w, acc);
    }
    __shared__ float red[256];
    red[t] = acc;
    __syncthreads();
#pragma unroll
    for (int sft = 128; sft > 0; sft >>= 1) {
        if (t < sft) red[t] += red[t + sft];
        __syncthreads();
    }
    if (t == 0) atomicAdd(&out[b*NCLS + c], red[0] + (s == 0 ? finb[c] : 0.f));
}

// ---------------------------------------------------------------------------
// Fused chord: ALL 13 rounds in one kernel.
// Block = (b, cp in 0..7) -> columns [cp*8, cp*8+8). 512 threads.
// smem (floats): Zs 8 planes x 4096 | Vs 8 planes x 512 | Fs 512x16 | toks u16[4096]
// Thread owns rows {t, t+512, ..., t+3584}; round result in 64 regs, then
// barrier + writeback. Fs for next round prefetched to regs during compute.
// ---------------------------------------------------------------------------
__global__ __launch_bounds__(512, 1) void chord_all_kernel(
    const int* __restrict__ tok, float* __restrict__ outZ) {
    extern __shared__ float sm[];
    float* Zs = sm;                       // [c*4096 + i], 32768 floats
    float* Vs = sm + 32768;               // [c*512 + v], 4096 floats
    float* Fs = sm + 36864;               // [v*16 + l], 8192 floats
    unsigned short* toks = (unsigned short*)(sm + 45056);  // 4096 u16

    const int b  = blockIdx.x >> 3;
    const int cp = blockIdx.x & 7;
    const int c0 = cp * 8;
    const int t  = threadIdx.x;
    const int offs[NL] = {0,1,2,4,8,16,32,64,128,256,512,1024,2048};

    // stage tok
    const int* tkb = tok + (size_t)b*NS;
#pragma unroll
    for (int m = 0; m < 8; m++) toks[t + 512*m] = (unsigned short)tkb[t + 512*m];

    // stage Vs planes (this block's 8 columns)
    {
        const float4* Vt4 = (const float4*)g_Vtab;
        float4 a = Vt4[t*16 + cp*2];
        float4 d = Vt4[t*16 + cp*2 + 1];
        Vs[0*512 + t] = a.x; Vs[1*512 + t] = a.y;
        Vs[2*512 + t] = a.z; Vs[3*512 + t] = a.w;
        Vs[4*512 + t] = d.x; Vs[5*512 + t] = d.y;
        Vs[6*512 + t] = d.z; Vs[7*512 + t] = d.w;
    }
    // stage Fs for round 0
    {
        const float4* Fg = (const float4*)g_Ftab;   // k=0
        float4* Fs4 = (float4*)Fs;
#pragma unroll
        for (int j = 0; j < 4; j++) Fs4[t + 512*j] = Fg[t + 512*j];
    }
    __syncthreads();

    // Z := V (gathered)
#pragma unroll
    for (int m = 0; m < 8; m++) {
        int i = t + 512*m;
        int v = toks[i];
#pragma unroll
        for (int c = 0; c < 8; c++) Zs[c*4096 + i] = Vs[c*512 + v];
    }
    __syncthreads();

    float acc[8][8];
#pragma unroll 1
    for (int k = 0; k < NWR; k++) {
        // prefetch next round's Ftab slice into regs
        float4 fnext[4];
        if (k < NWR - 1) {
            const float4* Fg = (const float4*)(g_Ftab + (size_t)(k+1)*VOCAB*16);
#pragma unroll
            for (int j = 0; j < 4; j++) fnext[j] = Fg[t + 512*j];
        }
        // compute Z_new into registers
#pragma unroll
        for (int m = 0; m < 8; m++) {
            const int i = t + 512*m;
            const int v = toks[i];
            const float4* frow = (const float4*)(Fs + v*16);
            float4 f0 = frow[0], f1 = frow[1], f2 = frow[2], f3 = frow[3];
            const float f[NL] = {f0.x,f0.y,f0.z,f0.w, f1.x,f1.y,f1.z,f1.w,
                                 f2.x,f2.y,f2.z,f2.w, f3.x};
            // residual +V
#pragma unroll
            for (int c = 0; c < 8; c++) acc[m][c] = Vs[c*512 + v];
#pragma unroll
            for (int l = 0; l < NL; l++) {
                const int j = (i + offs[l]) & (NS - 1);
                const float fl = f[l];
#pragma unroll
                for (int c = 0; c < 8; c++)
                    acc[m][c] = fmaf(fl, Zs[c*4096 + j], acc[m][c]);
            }
        }
        __syncthreads();
        // writeback + stage next Fs
#pragma unroll
        for (int m = 0; m < 8; m++) {
            int i = t + 512*m;
#pragma unroll
            for (int c = 0; c < 8; c++) Zs[c*4096 + i] = acc[m][c];
        }
        if (k < NWR - 1) {
            float4* Fs4 = (float4*)Fs;
#pragma unroll
            for (int j = 0; j < 4; j++) Fs4[t + 512*j] = fnext[j];
        }
        __syncthreads();
    }

    // final Z (still in acc regs) -> gmem
    float4* oz = (float4*)(outZ + ((size_t)b*NS)*64 + c0);
#pragma unroll
    for (int m = 0; m < 8; m++) {
        int i = t + 512*m;
        float4 o0 = make_float4(acc[m][0], acc[m][1], acc[m][2], acc[m][3]);
        float4 o1 = make_float4(acc[m][4], acc[m][5], acc[m][6], acc[m][7]);
        oz[(size_t)i*16]     = o0;
        oz[(size_t)i*16 + 1] = o1;
    }
}

// ---------------------------------------------------------------------------
extern "C" void kernel_launch(void* const* d_in, const int* in_sizes, int n_in,
                              void* d_out, int out_size) {
    const int*   tok  = (const int*)  d_in[0];
    const float* emb  = (const float*)d_in[1];
    const float* fW1  = (const float*)d_in[2];
    const float* fb1  = (const float*)d_in[3];
    const float* fW2  = (const float*)d_in[4];
    const float* fb2  = (const float*)d_in[5];
    const float* vW1  = (const float*)d_in[6];
    const float* vb1  = (const float*)d_in[7];
    const float* vW2  = (const float*)d_in[8];
    const float* vb2  = (const float*)d_in[9];
    const float* finW = (const float*)d_in[10];
    const float* finb = (const float*)d_in[11];
    float* out = (float*)d_out;

    const int tables_smem = (8192 + 8192 + 16384 + 8192) * 4;        // 163840
    const int chord_smem  = 45056 * 4 + 4096 * 2;                    // 188416
    cudaFuncSetAttribute(tables_kernel,    cudaFuncAttributeMaxDynamicSharedMemorySize, tables_smem);
    cudaFuncSetAttribute(chord_all_kernel, cudaFuncAttributeMaxDynamicSharedMemorySize, chord_smem);

    // 1. tables
    dim3 tgrid(4, 14);
    tables_kernel<<<tgrid, 128, tables_smem>>>(emb, fW1, fb1, fW2, fb2,
                                               vW1, vb1, vW2, vb2);
    // 2. logits
    cudaMemsetAsync(out, 0, NB*NCLS*sizeof(float));
    logits_kernel<<<NB*NCLS*8, 256>>>(tok, finW, finb, out);

    // 3. fused chord (writes Z directly into d_out after the logits)
    float* zdst;
    if (out_size >= NB*NCLS + ROWS*ND) zdst = out + NB*NCLS;
    else cudaGetSymbolAddress((void**)&zdst, g_Zdump);
    chord_all_kernel<<<NB*8, 512, chord_smem>>>(tok, zdst);
}

// round 4
// speedup vs baseline: 5.7834x; 1.2341x over previous
#include <cuda_runtime.h>
#include <math.h>

#define NB   32
#define NS   4096
#define ND   64
#define NL   13
#define NWR  13
#define NCLS 2
#define ROWS (NB*NS)          // 131072
#define SD   (NS*ND)          // 262144
#define VOCAB 512
#define FPAD 20               // Ftab row stride (floats)

__device__ float g_Vtab[VOCAB*ND];                    // [v][64]
__device__ float g_Ftab[(size_t)NWR*VOCAB*FPAD];      // [k][v][20] (13 used)
__device__ float g_Zdump[(size_t)ROWS*ND];            // fallback Z sink

__device__ __forceinline__ float gelu_exact(float x) {
    return 0.5f * x * (1.0f + erff(x * 0.7071067811865476f));
}

// ---------------------------------------------------------------------------
// Tables: grid (16, 14), block 256. y==0 -> Vtab, y==1..13 -> Ftab[y-1].
// 32 vocab rows per block. smem: Es(32x64) W1s(64x128) Hs(128x33) W2s(<=128x64)
// ---------------------------------------------------------------------------
__global__ __launch_bounds__(256) void tables_kernel(
    const float* __restrict__ emb,
    const float* __restrict__ fW1, const float* __restrict__ fb1,
    const float* __restrict__ fW2, const float* __restrict__ fb2,
    const float* __restrict__ vW1, const float* __restrict__ vb1,
    const float* __restrict__ vW2, const float* __restrict__ vb2) {
    extern __shared__ float sm[];
    float* Es  = sm;                    // 2048
    float* W1s = sm + 2048;             // 8192
    float* Hs  = sm + 10240;            // 128*33 = 4224
    float* W2s = sm + 14464;            // up to 8192

    const int y  = blockIdx.y;
    const int v0 = blockIdx.x * 32;
    const int t  = threadIdx.x;

    for (int i = t; i < 2048; i += 256) Es[i] = emb[v0*64 + i];
    const float* W1g = (y == 0) ? vW1 : fW1 + (size_t)(y-1)*64*128;
    for (int i = t; i < 8192; i += 256) W1s[i] = W1g[i];
    if (y == 0) {
        for (int i = t; i < 8192; i += 256) W2s[i] = vW2[i];
    } else {
        const float* W2g = fW2 + (size_t)(y-1)*128*NL;
        for (int i = t; i < 128*NL; i += 256) W2s[i] = W2g[i];
    }
    __syncthreads();

    // stage 1: Hs[h][r] = gelu(Es[r,:] . W1[:,h] + b1[h]), W1 col in regs
    {
        const int h  = t & 127;
        const int rg = t >> 7;          // 0..1 -> 16 rows each
        float w[64];
#pragma unroll
        for (int d = 0; d < 64; d++) w[d] = W1s[d*128 + h];
        const float b1 = (y == 0) ? vb1[h] : fb1[(y-1)*128 + h];
#pragma unroll 1
        for (int rr = 0; rr < 16; rr++) {
            int r = rg*16 + rr;
            float acc = b1;
#pragma unroll
            for (int d = 0; d < 64; d++) acc = fmaf(Es[r*64 + d], w[d], acc);
            Hs[h*33 + r] = gelu_exact(acc);
        }
    }
    __syncthreads();

    if (y == 0) {
        const int d = t & 63, rgrp = t >> 6;   // 4 groups x 8 rows
#pragma unroll 1
        for (int rr = 0; rr < 8; rr++) {
            int r = rgrp*8 + rr;
            float acc = vb2[d];
#pragma unroll 8
            for (int h2 = 0; h2 < 128; h2++)
                acc = fmaf(Hs[h2*33 + r], W2s[h2*64 + d], acc);
            g_Vtab[(size_t)(v0 + r)*64 + d] = acc;
        }
    } else {
        const int k = y - 1;
        for (int o = t; o < 32*NL + 0; o += 256) {
            // o = l*32 + r layout so l uniform per warp, r lane-consecutive
            if (o < 13*32) {
                int l = o >> 5, r = o & 31;
                float acc = fb2[k*NL + l];
#pragma unroll 8
                for (int h2 = 0; h2 < 128; h2++)
                    acc = fmaf(Hs[h2*33 + r], W2s[h2*NL + l], acc);
                g_Ftab[((size_t)k*VOCAB + v0 + r)*FPAD + l] = acc;
            }
        }
    }
}

// ---------------------------------------------------------------------------
// Logits: out[b,c] = sum_s Vtab[tok[b,s]] . finW[c, s*64:(s+1)*64] + finb[c]
// ---------------------------------------------------------------------------
__global__ __launch_bounds__(256) void logits_kernel(
    const int* __restrict__ tok,
    const float* __restrict__ finW, const float* __restrict__ finb,
    float* __restrict__ out) {
    const int s = blockIdx.x & 7;
    const int c = (blockIdx.x >> 3) & 1;
    const int b = blockIdx.x >> 4;
    const int t = threadIdx.x;
    const int chunk = SD/4/8;   // 8192 float4

    const float4* Vt4 = (const float4*)g_Vtab;
    const float4* w   = (const float4*)(finW + (size_t)c*SD) + s*chunk;
    const int*    tkb = tok + (size_t)b*NS;

    float acc = 0.f;
    for (int i = t; i < chunk; i += 256) {
        int gi   = s*chunk + i;
        int srow = gi >> 4;
        int d4   = gi & 15;
        float4 vv = Vt4[tkb[srow]*16 + d4];
        float4 ww = w[i];
        acc = fmaf(vv.x, ww.x, acc);
        acc = fmaf(vv.y, ww.y, acc);
        acc = fmaf(vv.z, ww.z, acc);
        acc = fmaf(vv.w, ww.w, acc);
    }
    __shared__ float red[256];
    red[t] = acc;
    __syncthreads();
#pragma unroll
    for (int sft = 128; sft > 0; sft >>= 1) {
        if (t < sft) red[t] += red[t + sft];
        __syncthreads();
    }
    if (t == 0) atomicAdd(&out[b*NCLS + c], red[0] + (s == 0 ? finb[c] : 0.f));
}

// ---------------------------------------------------------------------------
// Fused chord, all 13 rounds. Block = (b, cp 0..15) -> 4 columns.
// Thread t owns rows 8t..8t+7 (consecutive!), Z held in regs across rounds.
// Zs transposed: Zs[c*4096 + rho*512 + tt] = Z[8*tt + rho][cp*4 + c].
// Links 0/1/2/4 come from own regs (boundary rows from smem).
// ---------------------------------------------------------------------------
__global__ __launch_bounds__(512, 1) void chord_all_kernel(
    const int* __restrict__ tok, float* __restrict__ outZ) {
    extern __shared__ float sm[];
    float* Zs = sm;                 // 4*4096 = 16384
    float* Fs = sm + 16384;         // 512*20 = 10240
    float* Vs = sm + 26624;         // 512*5  = 2560

    const int b   = blockIdx.x >> 4;
    const int cp  = blockIdx.x & 15;
    const int t   = threadIdx.x;
    const int tp1 = (t + 1) & 511;
    int tts[9];
#pragma unroll
    for (int li = 0; li < 9; li++) tts[li] = (t + (1 << li)) & 511;

    // own-row tokens
    int v[8];
    {
        const int4* tkb = (const int4*)(tok + (size_t)b*NS + t*8);
        int4 a = tkb[0], d = tkb[1];
        v[0]=a.x; v[1]=a.y; v[2]=a.z; v[3]=a.w;
        v[4]=d.x; v[5]=d.y; v[6]=d.z; v[7]=d.w;
    }
    // stage Vs (this block's 4 cols), pad-5 rows
    {
        float4 a = ((const float4*)g_Vtab)[t*16 + cp];
        Vs[t*5+0]=a.x; Vs[t*5+1]=a.y; Vs[t*5+2]=a.z; Vs[t*5+3]=a.w;
    }
    // stage Fs round 0
    {
        const float4* Fg = (const float4*)g_Ftab;
        float4* Fs4 = (float4*)Fs;
#pragma unroll
        for (int j = 0; j < 5; j++) Fs4[t + 512*j] = Fg[t + 512*j];
    }
    __syncthreads();

    // Z := V
    float zreg[8][4];
#pragma unroll
    for (int r = 0; r < 8; r++)
#pragma unroll
        for (int c = 0; c < 4; c++) {
            zreg[r][c] = Vs[v[r]*5 + c];
            Zs[c*4096 + r*512 + t] = zreg[r][c];
        }
    __syncthreads();

    float acc[8][4];
#pragma unroll 1
    for (int k = 0; k < NWR; k++) {
#pragma unroll
        for (int r = 0; r < 8; r++) {
            const float4* frow = (const float4*)(Fs + v[r]*FPAD);
            float4 f0 = frow[0], f1 = frow[1], f2 = frow[2];
            float f[13] = {f0.x,f0.y,f0.z,f0.w, f1.x,f1.y,f1.z,f1.w,
                           f2.x,f2.y,f2.z,f2.w, (Fs + v[r]*FPAD)[12]};
            // residual + link 0 (own reg)
#pragma unroll
            for (int c = 0; c < 4; c++)
                acc[r][c] = fmaf(f[0], zreg[r][c], Vs[v[r]*5 + c]);
            // link off=1
            if (r < 7) {
#pragma unroll
                for (int c = 0; c < 4; c++)
                    acc[r][c] = fmaf(f[1], zreg[r+1][c], acc[r][c]);
            } else {
#pragma unroll
                for (int c = 0; c < 4; c++)
                    acc[r][c] = fmaf(f[1], Zs[c*4096 + 0*512 + tp1], acc[r][c]);
            }
            // link off=2
            if (r < 6) {
#pragma unroll
                for (int c = 0; c < 4; c++)
                    acc[r][c] = fmaf(f[2], zreg[r+2][c], acc[r][c]);
            } else {
#pragma unroll
                for (int c = 0; c < 4; c++)
                    acc[r][c] = fmaf(f[2], Zs[c*4096 + (r-6)*512 + tp1], acc[r][c]);
            }
            // link off=4
            if (r < 4) {
#pragma unroll
                for (int c = 0; c < 4; c++)
                    acc[r][c] = fmaf(f[3], zreg[r+4][c], acc[r][c]);
            } else {
#pragma unroll
                for (int c = 0; c < 4; c++)
                    acc[r][c] = fmaf(f[3], Zs[c*4096 + (r-4)*512 + tp1], acc[r][c]);
            }
            // far links off=8..2048 : rho = r, thread t + off/8
#pragma unroll
            for (int li = 0; li < 9; li++) {
                const int tt = tts[li];
#pragma unroll
                for (int c = 0; c < 4; c++)
                    acc[r][c] = fmaf(f[4+li], Zs[c*4096 + r*512 + tt], acc[r][c]);
            }
        }
        __syncthreads();   // all reads of old Zs / Fs done

        if (k < NWR - 1) {
            // issue next-round F loads early (L2-hot table)
            float4 fn[5];
            const float4* Fg = (const float4*)(g_Ftab + (size_t)(k+1)*VOCAB*FPAD);
#pragma unroll
            for (int j = 0; j < 5; j++) fn[j] = Fg[t + 512*j];
            // writeback Z
#pragma unroll
            for (int r = 0; r < 8; r++)
#pragma unroll
                for (int c = 0; c < 4; c++) {
                    Zs[c*4096 + r*512 + t] = acc[r][c];
                    zreg[r][c] = acc[r][c];
                }
            float4* Fs4 = (float4*)Fs;
#pragma unroll
            for (int j = 0; j < 5; j++) Fs4[t + 512*j] = fn[j];
            __syncthreads();
        }
    }

    // final Z -> gmem
#pragma unroll
    for (int r = 0; r < 8; r++)
        ((float4*)outZ)[((size_t)(b*NS + t*8 + r))*16 + cp] =
            make_float4(acc[r][0], acc[r][1], acc[r][2], acc[r][3]);
}

// ---------------------------------------------------------------------------
extern "C" void kernel_launch(void* const* d_in, const int* in_sizes, int n_in,
                              void* d_out, int out_size) {
    const int*   tok  = (const int*)  d_in[0];
    const float* emb  = (const float*)d_in[1];
    const float* fW1  = (const float*)d_in[2];
    const float* fb1  = (const float*)d_in[3];
    const float* fW2  = (const float*)d_in[4];
    const float* fb2  = (const float*)d_in[5];
    const float* vW1  = (const float*)d_in[6];
    const float* vb1  = (const float*)d_in[7];
    const float* vW2  = (const float*)d_in[8];
    const float* vb2  = (const float*)d_in[9];
    const float* finW = (const float*)d_in[10];
    const float* finb = (const float*)d_in[11];
    float* out = (float*)d_out;

    const int tables_smem = (2048 + 8192 + 4224 + 8192) * 4;   // 90624
    const int chord_smem  = (16384 + 10240 + 2560) * 4;        // 116736
    cudaFuncSetAttribute(tables_kernel,    cudaFuncAttributeMaxDynamicSharedMemorySize, tables_smem);
    cudaFuncSetAttribute(chord_all_kernel, cudaFuncAttributeMaxDynamicSharedMemorySize, chord_smem);

    dim3 tgrid(16, 14);
    tables_kernel<<<tgrid, 256, tables_smem>>>(emb, fW1, fb1, fW2, fb2,
                                               vW1, vb1, vW2, vb2);

    cudaMemsetAsync(out, 0, NB*NCLS*sizeof(float));
    logits_kernel<<<NB*NCLS*8, 256>>>(tok, finW, finb, out);

    float* zdst;
    if (out_size >= NB*NCLS + ROWS*ND) zdst = out + NB*NCLS;
    else cudaGetSymbolAddress((void**)&zdst, g_Zdump);
    chord_all_kernel<<<NB*16, 512, chord_smem>>>(tok, zdst);
}

// round 5
// speedup vs baseline: 6.3083x; 1.0908x over previous
#include <cuda_runtime.h>
#include <math.h>

#define NB   32
#define NS   4096
#define ND   64
#define NL   13
#define NWR  13
#define NCLS 2
#define ROWS (NB*NS)          // 131072
#define SD   (NS*ND)          // 262144
#define VOCAB 512

__device__ float g_Vtab[VOCAB*ND];                       // [v][64]
__device__ float g_Ftab[(size_t)NWR*VOCAB*16];           // [k][v][16] (13 used)
__device__ float g_FgT[(size_t)NWR*NB*NL*NS];            // [k][b][l][i]  88.6 MB
__device__ float g_Zdump[(size_t)ROWS*ND];               // fallback Z sink

__device__ __forceinline__ float gelu_exact(float x) {
    return 0.5f * x * (1.0f + erff(x * 0.7071067811865476f));
}

// ---------------------------------------------------------------------------
// Tables: grid (16, 14), block 512. y==0 -> Vtab, y==1..13 -> Ftab[y-1].
// 32 vocab rows/block. smem: Es(32x64) W1s(64x128) Hs(128x33) W2s(<=128x64)
// ---------------------------------------------------------------------------
__global__ __launch_bounds__(512) void tables_kernel(
    const float* __restrict__ emb,
    const float* __restrict__ fW1, const float* __restrict__ fb1,
    const float* __restrict__ fW2, const float* __restrict__ fb2,
    const float* __restrict__ vW1, const float* __restrict__ vb1,
    const float* __restrict__ vW2, const float* __restrict__ vb2) {
    extern __shared__ float sm[];
    float* Es  = sm;                    // 2048
    float* W1s = sm + 2048;             // 8192
    float* Hs  = sm + 10240;            // 128*33 = 4224
    float* W2s = sm + 14464;            // up to 8192

    const int y  = blockIdx.y;
    const int v0 = blockIdx.x * 32;
    const int t  = threadIdx.x;

    for (int i = t; i < 2048; i += 512) Es[i] = emb[v0*64 + i];
    const float* W1g = (y == 0) ? vW1 : fW1 + (size_t)(y-1)*64*128;
    for (int i = t; i < 8192; i += 512) W1s[i] = W1g[i];
    if (y == 0) {
        for (int i = t; i < 8192; i += 512) W2s[i] = vW2[i];
    } else {
        const float* W2g = fW2 + (size_t)(y-1)*128*NL;
        for (int i = t; i < 128*NL; i += 512) W2s[i] = W2g[i];
    }
    __syncthreads();

    // stage 1: Hs[h][r] = gelu(Es[r,:] . W1[:,h] + b1[h])
    {
        const int h  = t & 127;
        const int rg = t >> 7;          // 0..3 -> 8 rows each
        float w[64];
#pragma unroll
        for (int d = 0; d < 64; d++) w[d] = W1s[d*128 + h];
        const float b1 = (y == 0) ? vb1[h] : fb1[(y-1)*128 + h];
#pragma unroll 1
        for (int rr = 0; rr < 8; rr++) {
            int r = rg*8 + rr;
            float acc = b1;
#pragma unroll
            for (int d = 0; d < 64; d++) acc = fmaf(Es[r*64 + d], w[d], acc);
            Hs[h*33 + r] = gelu_exact(acc);
        }
    }
    __syncthreads();

    if (y == 0) {
        const int d = t & 63, rgrp = t >> 6;   // 8 groups x 4 rows
#pragma unroll 1
        for (int rr = 0; rr < 4; rr++) {
            int r = rgrp*4 + rr;
            float acc = vb2[d];
#pragma unroll 8
            for (int h2 = 0; h2 < 128; h2++)
                acc = fmaf(Hs[h2*33 + r], W2s[h2*64 + d], acc);
            g_Vtab[(size_t)(v0 + r)*64 + d] = acc;
        }
    } else {
        const int k = y - 1;
        if (t < 32*NL) {
            int l = t >> 5, r = t & 31;
            float acc = fb2[k*NL + l];
#pragma unroll 8
            for (int h2 = 0; h2 < 128; h2++)
                acc = fmaf(Hs[h2*33 + r], W2s[h2*NL + l], acc);
            g_Ftab[((size_t)k*VOCAB + v0 + r)*16 + l] = acc;
        }
    }
}

// ---------------------------------------------------------------------------
// F expansion: FgT[k][b][l][i] = Ftab[k][tok[b][i]][l]
// grid (NS/256, NWR*NB, 4), block 256. z handles l = 4z..4z+3 via one float4.
// ---------------------------------------------------------------------------
__global__ __launch_bounds__(256) void fgather_kernel(const int* __restrict__ tok) {
    const int i  = blockIdx.x * 256 + threadIdx.x;
    const int kb = blockIdx.y;          // k*NB + b
    const int k  = kb >> 5;
    const int b  = kb & 31;
    const int z  = blockIdx.z;          // l-group
    const int v  = tok[(size_t)b*NS + i];

    float4 fv = ((const float4*)g_Ftab)[((size_t)k*VOCAB + v)*4 + z];
    float* dst = g_FgT + ((size_t)kb*NL)*NS + i;
    const int lmax = (z == 3) ? 1 : 4;
    if (lmax > 0) dst[(size_t)(z*4+0)*NS] = fv.x;
    if (z < 3) {
        dst[(size_t)(z*4+1)*NS] = fv.y;
        dst[(size_t)(z*4+2)*NS] = fv.z;
        dst[(size_t)(z*4+3)*NS] = fv.w;
    }
}

// ---------------------------------------------------------------------------
// Logits
// ---------------------------------------------------------------------------
__global__ __launch_bounds__(256) void logits_kernel(
    const int* __restrict__ tok,
    const float* __restrict__ finW, const float* __restrict__ finb,
    float* __restrict__ out) {
    const int s = blockIdx.x & 7;
    const int c = (blockIdx.x >> 3) & 1;
    const int b = blockIdx.x >> 4;
    const int t = threadIdx.x;
    const int chunk = SD/4/8;   // 8192 float4

    const float4* Vt4 = (const float4*)g_Vtab;
    const float4* w   = (const float4*)(finW + (size_t)c*SD) + s*chunk;
    const int*    tkb = tok + (size_t)b*NS;

    float acc = 0.f;
    for (int i = t; i < chunk; i += 256) {
        int gi   = s*chunk + i;
        int srow = gi >> 4;
        int d4   = gi & 15;
        float4 vv = Vt4[tkb[srow]*16 + d4];
        float4 ww = w[i];
        acc = fmaf(vv.x, ww.x, acc);
        acc = fmaf(vv.y, ww.y, acc);
        acc = fmaf(vv.z, ww.z, acc);
        acc = fmaf(vv.w, ww.w, acc);
    }
    __shared__ float red[256];
    red[t] = acc;
    __syncthreads();
#pragma unroll
    for (int sft = 128; sft > 0; sft >>= 1) {
        if (t < sft) red[t] += red[t + sft];
        __syncthreads();
    }
    if (t == 0) atomicAdd(&out[b*NCLS + c], red[0] + (s == 0 ? finb[c] : 0.f));
}

// ---------------------------------------------------------------------------
// Fused chord, all 13 rounds. Block = (b, cp 0..7) -> 8 columns c0=cp*8.
// Thread t owns rows i = t + 512m (m=0..7); links 0/512/1024/2048 come from
// own registers (zregA/B); links 1..256 from float4 smem planes ZsA/ZsB.
// F coefficients read coalesced from pre-expanded g_FgT (L2).
// ---------------------------------------------------------------------------
__global__ __launch_bounds__(512, 1) void chord_all_kernel(
    const int* __restrict__ tok, float* __restrict__ outZ) {
    extern __shared__ float sm[];
    float4* ZsA = (float4*)sm;            // [i] cols c0..c0+3
    float4* ZsB = ZsA + NS;               // [i] cols c0+4..c0+7
    float*  Vs  = (float*)(ZsB + NS);     // [v*9 + c], 512*9

    const int b  = blockIdx.x >> 3;
    const int cp = blockIdx.x & 7;
    const int c0 = cp * 8;
    const int t  = threadIdx.x;

    // own-row tokens
    int v[8];
    {
        const int* tkb = tok + (size_t)b*NS;
#pragma unroll
        for (int m = 0; m < 8; m++) v[m] = tkb[t + 512*m];
    }
    // stage Vs: Vs[v*9 + c] = Vtab[v][c0+c]
    {
        const float4* Vt4 = (const float4*)(g_Vtab + (size_t)t*64 + c0);
        float4 a = Vt4[0], d = Vt4[1];
        float* dst = Vs + t*9;
        dst[0]=a.x; dst[1]=a.y; dst[2]=a.z; dst[3]=a.w;
        dst[4]=d.x; dst[5]=d.y; dst[6]=d.z; dst[7]=d.w;
    }
    __syncthreads();

    // Z := V
    float4 zregA[8], zregB[8];
#pragma unroll
    for (int m = 0; m < 8; m++) {
        const float* vv = Vs + v[m]*9;
        zregA[m] = make_float4(vv[0], vv[1], vv[2], vv[3]);
        zregB[m] = make_float4(vv[4], vv[5], vv[6], vv[7]);
        ZsA[t + 512*m] = zregA[m];
        ZsB[t + 512*m] = zregB[m];
    }
    __syncthreads();

    float4 accA[8], accB[8];
#pragma unroll 1
    for (int k = 0; k < NWR; k++) {
        const float* Fbase = g_FgT + ((size_t)(k*NB + b)*NL)*NS + t;
#pragma unroll
        for (int m = 0; m < 8; m++) {
            const int i = t + 512*m;
            const float* fp = Fbase + 512*m;
            float f0  = fp[0];
            float f1  = fp[(size_t)1*NS],  f2  = fp[(size_t)2*NS];
            float f3  = fp[(size_t)3*NS],  f4  = fp[(size_t)4*NS];
            float f5  = fp[(size_t)5*NS],  f6  = fp[(size_t)6*NS];
            float f7  = fp[(size_t)7*NS],  f8  = fp[(size_t)8*NS];
            float f9  = fp[(size_t)9*NS],  f10 = fp[(size_t)10*NS];
            float f11 = fp[(size_t)11*NS], f12 = fp[(size_t)12*NS];

            const float* vv = Vs + v[m]*9;
            float4 aA = make_float4(vv[0], vv[1], vv[2], vv[3]);
            float4 aB = make_float4(vv[4], vv[5], vv[6], vv[7]);

            // own-register links: off 0, 512, 1024, 2048
            const int m1 = (m+1)&7, m2 = (m+2)&7, m4 = (m+4)&7;
            aA.x = fmaf(f0,  zregA[m ].x, aA.x); aA.y = fmaf(f0,  zregA[m ].y, aA.y);
            aA.z = fmaf(f0,  zregA[m ].z, aA.z); aA.w = fmaf(f0,  zregA[m ].w, aA.w);
            aB.x = fmaf(f0,  zregB[m ].x, aB.x); aB.y = fmaf(f0,  zregB[m ].y, aB.y);
            aB.z = fmaf(f0,  zregB[m ].z, aB.z); aB.w = fmaf(f0,  zregB[m ].w, aB.w);
            aA.x = fmaf(f10, zregA[m1].x, aA.x); aA.y = fmaf(f10, zregA[m1].y, aA.y);
            aA.z = fmaf(f10, zregA[m1].z, aA.z); aA.w = fmaf(f10, zregA[m1].w, aA.w);
            aB.x = fmaf(f10, zregB[m1].x, aB.x); aB.y = fmaf(f10, zregB[m1].y, aB.y);
            aB.z = fmaf(f10, zregB[m1].z, aB.z); aB.w = fmaf(f10, zregB[m1].w, aB.w);
            aA.x = fmaf(f11, zregA[m2].x, aA.x); aA.y = fmaf(f11, zregA[m2].y, aA.y);
            aA.z = fmaf(f11, zregA[m2].z, aA.z); aA.w = fmaf(f11, zregA[m2].w, aA.w);
            aB.x = fmaf(f11, zregB[m2].x, aB.x); aB.y = fmaf(f11, zregB[m2].y, aB.y);
            aB.z = fmaf(f11, zregB[m2].z, aB.z); aB.w = fmaf(f11, zregB[m2].w, aB.w);
            aA.x = fmaf(f12, zregA[m4].x, aA.x); aA.y = fmaf(f12, zregA[m4].y, aA.y);
            aA.z = fmaf(f12, zregA[m4].z, aA.z); aA.w = fmaf(f12, zregA[m4].w, aA.w);
            aB.x = fmaf(f12, zregB[m4].x, aB.x); aB.y = fmaf(f12, zregB[m4].y, aB.y);
            aB.z = fmaf(f12, zregB[m4].z, aB.z); aB.w = fmaf(f12, zregB[m4].w, aB.w);

            // smem links: off 1..256
            const float fs[9] = {f1,f2,f3,f4,f5,f6,f7,f8,f9};
            const int offs[9] = {1,2,4,8,16,32,64,128,256};
#pragma unroll
            for (int li = 0; li < 9; li++) {
                const int j = (i + offs[li]) & (NS-1);
                const float fl = fs[li];
                float4 zA = ZsA[j], zB = ZsB[j];
                aA.x = fmaf(fl, zA.x, aA.x); aA.y = fmaf(fl, zA.y, aA.y);
                aA.z = fmaf(fl, zA.z, aA.z); aA.w = fmaf(fl, zA.w, aA.w);
                aB.x = fmaf(fl, zB.x, aB.x); aB.y = fmaf(fl, zB.y, aB.y);
                aB.z = fmaf(fl, zB.z, aB.z); aB.w = fmaf(fl, zB.w, aB.w);
            }
            accA[m] = aA; accB[m] = aB;
        }
        if (k < NWR - 1) {
            __syncthreads();
#pragma unroll
            for (int m = 0; m < 8; m++) {
                ZsA[t + 512*m] = accA[m];
                ZsB[t + 512*m] = accB[m];
                zregA[m] = accA[m];
                zregB[m] = accB[m];
            }
            __syncthreads();
        }
    }

    // final Z -> gmem: out[i*64 + c0 .. c0+7] contiguous 32B per row
#pragma unroll
    for (int m = 0; m < 8; m++) {
        const int i = t + 512*m;
        float4* dst = (float4*)(outZ + ((size_t)b*NS + i)*64 + c0);
        dst[0] = accA[m];
        dst[1] = accB[m];
    }
}

// ---------------------------------------------------------------------------
extern "C" void kernel_launch(void* const* d_in, const int* in_sizes, int n_in,
                              void* d_out, int out_size) {
    const int*   tok  = (const int*)  d_in[0];
    const float* emb  = (const float*)d_in[1];
    const float* fW1  = (const float*)d_in[2];
    const float* fb1  = (const float*)d_in[3];
    const float* fW2  = (const float*)d_in[4];
    const float* fb2  = (const float*)d_in[5];
    const float* vW1  = (const float*)d_in[6];
    const float* vb1  = (const float*)d_in[7];
    const float* vW2  = (const float*)d_in[8];
    const float* vb2  = (const float*)d_in[9];
    const float* finW = (const float*)d_in[10];
    const float* finb = (const float*)d_in[11];
    float* out = (float*)d_out;

    const int tables_smem = (2048 + 8192 + 4224 + 8192) * 4;       // 90624
    const int chord_smem  = (NS*4 + NS*4 + VOCAB*9) * 4;           // 149504
    cudaFuncSetAttribute(tables_kernel,    cudaFuncAttributeMaxDynamicSharedMemorySize, tables_smem);
    cudaFuncSetAttribute(chord_all_kernel, cudaFuncAttributeMaxDynamicSharedMemorySize, chord_smem);

    dim3 tgrid(16, 14);
    tables_kernel<<<tgrid, 512, tables_smem>>>(emb, fW1, fb1, fW2, fb2,
                                               vW1, vb1, vW2, vb2);

    dim3 fggrid(NS/256, NWR*NB, 4);
    fgather_kernel<<<fggrid, 256>>>(tok);

    cudaMemsetAsync(out, 0, NB*NCLS*sizeof(float));
    logits_kernel<<<NB*NCLS*8, 256>>>(tok, finW, finb, out);

    float* zdst;
    if (out_size >= NB*NCLS + ROWS*ND) zdst = out + NB*NCLS;
    else cudaGetSymbolAddress((void**)&zdst, g_Zdump);
    chord_all_kernel<<<NB*8, 512, chord_smem>>>(tok, zdst);
}